// round 5
// baseline (speedup 1.0000x reference)
#include <cuda_runtime.h>
#include <cstdint>

typedef unsigned long long ull;

#define L2E 1.4426950408889634f
#define LN2 0.6931471805599453f

// Inter-kernel scratch (static device memory: allowed)
__device__ float g_l128[(size_t)512 * 128 * 32];   // 8 MB
__device__ float g_l8 [(size_t)512 * 8 * 32];      // 512 KB

// ---------------------------------------------------------------------------
// Low-level helpers
// ---------------------------------------------------------------------------
__device__ __forceinline__ float ex2f(float x) {
    float r; asm("ex2.approx.f32 %0, %1;" : "=f"(r) : "f"(x)); return r;
}
__device__ __forceinline__ float lg2f(float x) {
    float r; asm("lg2.approx.f32 %0, %1;" : "=f"(r) : "f"(x)); return r;
}
__device__ __forceinline__ ull pack2(float x) {
    ull r; asm("mov.b64 %0, {%1, %1};" : "=l"(r) : "f"(x)); return r;
}
__device__ __forceinline__ void unpack2(ull v, float& lo, float& hi) {
    asm("mov.b64 {%0, %1}, %2;" : "=f"(lo), "=f"(hi) : "l"(v));
}
__device__ __forceinline__ ull fma2(ull a, ull b, ull c) {
    ull d; asm("fma.rn.f32x2 %0, %1, %2, %3;" : "=l"(d) : "l"(a), "l"(b), "l"(c)); return d;
}
__device__ __forceinline__ void lds2(ull& a, ull& b, uint32_t addr) {
    asm("ld.shared.v2.u64 {%0, %1}, [%2];" : "=l"(a), "=l"(b) : "r"(addr));
}
__device__ __forceinline__ uint32_t s2u(const void* p) {
    return (uint32_t)__cvta_generic_to_shared(p);
}

// ---------------------------------------------------------------------------
// Core: thread = one batch, warp task = one (node, 32 batches).
//   p[k] in regs; m = max; e = exp(p-m); y = e @ W (f32x2-packed, W broadcast
//   from smem); out = log(y) + m. Natural-log values throughout; max is
//   subtracted before the log2 scaling (precision).
// ---------------------------------------------------------------------------
__device__ __forceinline__ void node_core(float p[32], uint32_t waddr,
                                          float* po, int ostr) {
    float m0 = p[0], m1 = p[1], m2 = p[2], m3 = p[3];
#pragma unroll
    for (int k = 4; k < 32; k += 4) {
        m0 = fmaxf(m0, p[k]);     m1 = fmaxf(m1, p[k + 1]);
        m2 = fmaxf(m2, p[k + 2]); m3 = fmaxf(m3, p[k + 3]);
    }
    const float mx = fmaxf(fmaxf(m0, m1), fmaxf(m2, m3));
    const float nmx = -mx * L2E;

#pragma unroll
    for (int k = 0; k < 32; k++) p[k] = ex2f(fmaf(p[k], L2E, nmx));  // p -> e

    ull acc[16];
#pragma unroll
    for (int q = 0; q < 16; q++) acc[q] = 0ULL;

#pragma unroll 4
    for (int i = 0; i < 32; i++) {
        const ull ep = pack2(p[i]);
        const uint32_t ra = waddr + (uint32_t)i * 128u;
#pragma unroll
        for (int q = 0; q < 8; q++) {
            ull w0, w1; lds2(w0, w1, ra + (uint32_t)q * 16u);
            acc[2 * q]     = fma2(ep, w0, acc[2 * q]);
            acc[2 * q + 1] = fma2(ep, w1, acc[2 * q + 1]);
        }
    }

#pragma unroll
    for (int q = 0; q < 16; q++) {
        float y0, y1; unpack2(acc[q], y0, y1);
        po[(2 * q)     * ostr] = fmaf(lg2f(y0), LN2, mx);
        po[(2 * q + 1) * ostr] = fmaf(lg2f(y1), LN2, mx);
    }
}

// Layer-0 variant: the two sibling leaf vectors are 64 contiguous floats.
__device__ __forceinline__ void node_g(const float* __restrict__ gp,
                                       uint32_t waddr, float* po, int ostr) {
    float p[32];
    const float4* g4 = (const float4*)gp;
#pragma unroll
    for (int q = 0; q < 8; q++) {
        float4 a = g4[q], bb = g4[q + 8];
        p[4 * q]     = a.x + bb.x; p[4 * q + 1] = a.y + bb.y;
        p[4 * q + 2] = a.z + bb.z; p[4 * q + 3] = a.w + bb.w;
    }
    node_core(p, waddr, po, ostr);
}

// Inner-layer variant: inputs from smem val buffer (element stride istr).
__device__ __forceinline__ void node_s(const float* sa, const float* sb, int istr,
                                       uint32_t waddr, float* po, int ostr) {
    float p[32];
#pragma unroll
    for (int k = 0; k < 32; k++) p[k] = sa[k * istr] + sb[k * istr];
    node_core(p, waddr, po, ostr);
}

// ---------------------------------------------------------------------------
// Tree kernel: 16-leaf subtree -> 1 node (4 layers), in place.
// Block: 8 warps, 64 batches. Grid: (IN_F/16 subtrees, 8 batch-groups).
// smem: val 8 slots x [32k x 64b] = 64KB; wbuf double buffer 2 x 16KB = 32KB.
// Weight prefetch: LDG->regs before compute, STS after -> latency hidden.
// ---------------------------------------------------------------------------
#define SMEM_TREE_FLOATS (8 * 2048 + 2 * 4096)   // 98304 bytes

template <int IN_F>
__global__ void __launch_bounds__(256, 2)
pc_tree(const float* __restrict__ in, const float* __restrict__ W,
        float* __restrict__ outp) {
    extern __shared__ float sm[];
    float* val = sm;                    // 8 x 2048 floats
    float* wb0 = sm + 16384;            // 4 x 1024
    float* wb1 = sm + 20480;            // 4 x 1024

    const int s   = blockIdx.x;
    const int B0  = blockIdx.y * 64;
    const int tid = threadIdx.x;
    const int w = tid >> 5, lane = tid & 31;
    const int bh = w & 1, jj = w >> 1;      // warp task coords
    const int b  = bh * 32 + lane;          // batch column 0..63

    const int o0 = 2048 - IN_F;
    const float* wsrc0 = W + (size_t)(o0 + s * 8) * 1024;
    const float* wsrc1 = wsrc0 + 4 * 1024;
    const float* wsrc2 = W + (size_t)(o0 + IN_F / 2 + s * 4) * 1024;
    const float* wsrc3 = W + (size_t)(o0 + IN_F / 2 + IN_F / 4 + s * 2) * 1024;
    const float* wsrc4 = W + (size_t)(o0 + IN_F / 2 + IN_F / 4 + IN_F / 8 + s) * 1024;

    // prologue: stage round-0 weights (4 matrices)
    {
        const float4* src = (const float4*)wsrc0;
        float4* dst = (float4*)wb0;
#pragma unroll
        for (int i = 0; i < 4; i++) dst[tid + i * 256] = src[tid + i * 256];
    }
    __syncthreads();

    const float* gbase = in + ((size_t)(B0 + b) * IN_F + s * 16) * 32;
    float4 pw[4];

    // ---- round 0: layer0 nodes 0..3 (j=jj, bh) ----
    {
        const float4* src = (const float4*)wsrc1;
#pragma unroll
        for (int i = 0; i < 4; i++) pw[i] = src[tid + i * 256];
    }
    node_g(gbase + jj * 64, s2u(wb0 + jj * 1024), val + jj * 2048 + b, 64);
    {
        float4* dst = (float4*)wb1;
#pragma unroll
        for (int i = 0; i < 4; i++) dst[tid + i * 256] = pw[i];
    }
    __syncthreads();

    // ---- round 1: layer0 nodes 4..7 ----
    {
        const float4* src = (const float4*)wsrc2;
#pragma unroll
        for (int i = 0; i < 4; i++) pw[i] = src[tid + i * 256];
    }
    node_g(gbase + (4 + jj) * 64, s2u(wb1 + jj * 1024), val + (4 + jj) * 2048 + b, 64);
    {
        float4* dst = (float4*)wb0;
#pragma unroll
        for (int i = 0; i < 4; i++) dst[tid + i * 256] = pw[i];
    }
    __syncthreads();

    // ---- round 2: layer1 node j=jj: slots 2j,2j+1 -> 2j ----
    {
        const float4* src = (const float4*)wsrc3;
#pragma unroll
        for (int i = 0; i < 2; i++) pw[i] = src[tid + i * 256];
    }
    node_s(val + (2 * jj) * 2048 + b, val + (2 * jj + 1) * 2048 + b, 64,
           s2u(wb0 + jj * 1024), val + (2 * jj) * 2048 + b, 64);
    {
        float4* dst = (float4*)wb1;
#pragma unroll
        for (int i = 0; i < 2; i++) dst[tid + i * 256] = pw[i];
    }
    __syncthreads();

    // ---- round 3: layer2, warps 0..3: j=jj(0..1): slots 4j,4j+2 -> 4j ----
    pw[0] = ((const float4*)wsrc4)[tid];
    if (w < 4)
        node_s(val + (4 * jj) * 2048 + b, val + (4 * jj + 2) * 2048 + b, 64,
               s2u(wb1 + jj * 1024), val + (4 * jj) * 2048 + b, 64);
    ((float4*)wb0)[tid] = pw[0];
    __syncthreads();

    // ---- round 4: layer3, warps 0..1: slots 0,4 -> 0 ----
    if (w < 2)
        node_s(val + b, val + 4 * 2048 + b, 64, s2u(wb0), val + b, 64);
    __syncthreads();

    // ---- write root (val slot 0, [k*64 + b]) coalesced-ish per-thread rows ----
    constexpr int OUT_F = IN_F / 16;
    {
        const int b2 = tid & 63, qk = tid >> 6;   // qk 0..3, k-range qk*8..+7
        float* op = outp + ((size_t)(B0 + b2) * OUT_F + s) * 32 + qk * 8;
        float4 v0, v1;
        v0.x = val[(qk * 8 + 0) * 64 + b2]; v0.y = val[(qk * 8 + 1) * 64 + b2];
        v0.z = val[(qk * 8 + 2) * 64 + b2]; v0.w = val[(qk * 8 + 3) * 64 + b2];
        v1.x = val[(qk * 8 + 4) * 64 + b2]; v1.y = val[(qk * 8 + 5) * 64 + b2];
        v1.z = val[(qk * 8 + 6) * 64 + b2]; v1.w = val[(qk * 8 + 7) * 64 + b2];
        *(float4*)op = v0; *((float4*)op + 1) = v1;
    }
}

// ---------------------------------------------------------------------------
// Tail: F=8 -> root + mixture. Grid 16 blocks x 256 thr, 32 batches each.
// smem: val 8 x [32k x 32b] = 32KB; all 7 weight matrices = 28KB; lw 32.
// ---------------------------------------------------------------------------
#define SMEM_TAIL_FLOATS (8 * 1024 + 7 * 1024 + 32)

__global__ void __launch_bounds__(256, 2)
pc_tail8(const float* __restrict__ in, const float* __restrict__ W,
         const float* __restrict__ mlw, float* __restrict__ outp) {
    extern __shared__ float sm[];
    float* val = sm;              // 8 x 1024
    float* wb  = sm + 8192;       // 7 x 1024
    float* lw  = sm + 8192 + 7168;

    const int B0  = blockIdx.x * 32;
    const int tid = threadIdx.x;
    const int w = tid >> 5, lane = tid & 31;

    {
        const float4* src = (const float4*)(W + (size_t)2040 * 1024);
        float4* dst = (float4*)wb;
#pragma unroll
        for (int i = 0; i < 7; i++) dst[tid + i * 256] = src[tid + i * 256];
    }
    if (tid < 32) lw[tid] = mlw[tid];
    __syncthreads();

    // layer F=4: warps 0..3: j=w, reads global nodes 2j,2j+1 -> slot j
    if (w < 4) {
        const float* gp = in + ((size_t)(B0 + lane) * 8 + 2 * w) * 32;
        node_g(gp, s2u(wb + w * 1024), val + w * 1024 + lane, 32);
    }
    __syncthreads();

    // layer F=2: warps 0..1: j=w: slots 2j,2j+1 -> 2j
    if (w < 2)
        node_s(val + (2 * w) * 1024 + lane, val + (2 * w + 1) * 1024 + lane, 32,
               s2u(wb + (4 + w) * 1024), val + (2 * w) * 1024 + lane, 32);
    __syncthreads();

    // layer F=1: warp 0: slots 0,2 -> 0
    if (w == 0)
        node_s(val + lane, val + 2 * 1024 + lane, 32,
               s2u(wb + 6 * 1024), val + lane, 32);
    __syncthreads();

    // mixture: out[b] = logsumexp(2*root + log_softmax(mlw))
    if (tid < 32) {
        const int b2 = tid;
        float m1 = lw[0];
        for (int k = 1; k < 32; k++) m1 = fmaxf(m1, lw[k]);
        float s1 = 0.f;
        for (int k = 0; k < 32; k++) s1 += ex2f((lw[k] - m1) * L2E);
        const float lse = fmaf(lg2f(s1), LN2, m1);

        float m2 = -1e30f;
        for (int k = 0; k < 32; k++)
            m2 = fmaxf(m2, 2.f * val[k * 32 + b2] + lw[k] - lse);
        float s2 = 0.f;
        for (int k = 0; k < 32; k++)
            s2 += ex2f((2.f * val[k * 32 + b2] + lw[k] - lse - m2) * L2E);
        outp[B0 + b2] = fmaf(lg2f(s2), LN2, m2);
    }
}

// ---------------------------------------------------------------------------
// Launch. Inputs: x f32[512,2048,32], weights f32[2047,32,32],
// fold_idx i32 (trivial (2f,2f+1) pairing -> computed), mix_logw f32[32].
// Output: f32[512].
// ---------------------------------------------------------------------------
extern "C" void kernel_launch(void* const* d_in, const int* in_sizes, int n_in,
                              void* d_out, int out_size) {
    const float* x   = (const float*)d_in[0];
    const float* W   = (const float*)d_in[1];
    const float* mlw = (const float*)d_in[3];
    float* out = (float*)d_out;

    float* g1; cudaGetSymbolAddress((void**)&g1, g_l128);
    float* g2; cudaGetSymbolAddress((void**)&g2, g_l8);

    const int smem_tree = SMEM_TREE_FLOATS * sizeof(float);
    const int smem_tail = SMEM_TAIL_FLOATS * sizeof(float);
    cudaFuncSetAttribute(pc_tree<2048>, cudaFuncAttributeMaxDynamicSharedMemorySize, smem_tree);
    cudaFuncSetAttribute(pc_tree<128>,  cudaFuncAttributeMaxDynamicSharedMemorySize, smem_tree);
    cudaFuncSetAttribute(pc_tail8,      cudaFuncAttributeMaxDynamicSharedMemorySize, smem_tail);

    pc_tree<2048><<<dim3(128, 8), 256, smem_tree>>>(x,  W, g1);
    pc_tree<128> <<<dim3(8, 8),   256, smem_tree>>>(g1, W, g2);
    pc_tail8     <<<16,           256, smem_tail>>>(g2, W, mlw, out);
}

// round 6
// speedup vs baseline: 1.8390x; 1.8390x over previous
#include <cuda_runtime.h>
#include <cstdint>

typedef unsigned long long ull;

#define L2E 1.4426950408889634f
#define LN2 0.6931471805599453f

// Inter-kernel scratch (static device memory: allowed)
__device__ float g_l128[(size_t)512 * 128 * 32];   // 8 MB
__device__ float g_l8 [(size_t)512 * 8 * 32];      // 512 KB

// ---------------------------------------------------------------------------
// Low-level helpers
// ---------------------------------------------------------------------------
__device__ __forceinline__ float ex2f(float x) {
    float r; asm("ex2.approx.f32 %0, %1;" : "=f"(r) : "f"(x)); return r;
}
__device__ __forceinline__ float lg2f(float x) {
    float r; asm("lg2.approx.f32 %0, %1;" : "=f"(r) : "f"(x)); return r;
}
__device__ __forceinline__ uint32_t cvt_tf32(float x) {
    uint32_t r; asm("cvt.rna.tf32.f32 %0, %1;" : "=r"(r) : "f"(x)); return r;
}
__device__ __forceinline__ uint32_t s2u(const void* p) {
    return (uint32_t)__cvta_generic_to_shared(p);
}
__device__ __forceinline__ ull pack2(float x) {
    ull r; asm("mov.b64 %0, {%1, %1};" : "=l"(r) : "f"(x)); return r;
}
__device__ __forceinline__ void unpack2(ull v, float& lo, float& hi) {
    asm("mov.b64 {%0, %1}, %2;" : "=f"(lo), "=f"(hi) : "l"(v));
}
__device__ __forceinline__ ull fma2(ull a, ull b, ull c) {
    ull d; asm("fma.rn.f32x2 %0, %1, %2, %3;" : "=l"(d) : "l"(a), "l"(b), "l"(c)); return d;
}
__device__ __forceinline__ void lds2(ull& a, ull& b, uint32_t addr) {
    asm("ld.shared.v2.u64 {%0, %1}, [%2];" : "=l"(a), "=l"(b) : "r"(addr));
}

// m16n8k8 tf32 mma, D += A*B
__device__ __forceinline__ void mma_tf32(float c[4], const uint32_t a[4], const uint32_t b[2]) {
    asm("mma.sync.aligned.m16n8k8.row.col.f32.tf32.tf32.f32 "
        "{%0,%1,%2,%3}, {%4,%5,%6,%7}, {%8,%9}, {%0,%1,%2,%3};"
        : "+f"(c[0]), "+f"(c[1]), "+f"(c[2]), "+f"(c[3])
        : "r"(a[0]), "r"(a[1]), "r"(a[2]), "r"(a[3]), "r"(b[0]), "r"(b[1]));
}

// ---------------------------------------------------------------------------
// MMA node: warp computes one node for 32 batches.
// Value slots: row-major [b*36 + k] (stride 36 -> conflict-free A-frag LDS).
// W slot: tf32 bits, row-major [k*36 + j].
//   p = A(+B); m = rowmax; e = exp2((p-m)*L2E); Y = e @ W; out = log2(Y)*LN2+m
// ---------------------------------------------------------------------------
#define SLOT_FL (32 * 36)        // 1152 floats per slot

template <bool DUAL>
__device__ __forceinline__ void node_mma(const float* pa, const float* pb,
                                         const float* wp, float* po, int lane) {
    const int g = lane >> 2, tg = lane & 3;

    // ---- A fragments: a[mt][kt][r], r: 0=(u0,v0) 1=(u1,v0) 2=(u0,v1) 3=(u1,v1)
    float a[2][4][4];
#pragma unroll
    for (int mt = 0; mt < 2; mt++)
#pragma unroll
        for (int kt = 0; kt < 4; kt++)
#pragma unroll
            for (int r = 0; r < 4; r++) {
                const int row = 16 * mt + 8 * (r & 1) + g;
                const int col = 8 * kt + 4 * (r >> 1) + tg;
                float v = pa[row * 36 + col];
                if (DUAL) v += pb[row * 36 + col];
                a[mt][kt][r] = v;
            }

    // ---- row max per (mt, u): local over 8 cols, then 4-lane shfl reduce
    float mx[2][2];
#pragma unroll
    for (int mt = 0; mt < 2; mt++)
#pragma unroll
        for (int u = 0; u < 2; u++) {
            float m = fmaxf(a[mt][0][u], a[mt][0][u + 2]);
#pragma unroll
            for (int kt = 1; kt < 4; kt++)
                m = fmaxf(m, fmaxf(a[mt][kt][u], a[mt][kt][u + 2]));
            m = fmaxf(m, __shfl_xor_sync(0xffffffffu, m, 1));
            m = fmaxf(m, __shfl_xor_sync(0xffffffffu, m, 2));
            mx[mt][u] = m;
        }

    // ---- e = exp2((p - m) * L2E), fed as tf32 bits (RZ truncate is fine: e<=1)
    uint32_t ua[2][4][4];
#pragma unroll
    for (int mt = 0; mt < 2; mt++)
#pragma unroll
        for (int kt = 0; kt < 4; kt++)
#pragma unroll
            for (int r = 0; r < 4; r++) {
                const float nm = -mx[mt][r & 1] * L2E;
                ua[mt][kt][r] = __float_as_uint(ex2f(fmaf(a[mt][kt][r], L2E, nm)));
            }

    // ---- B fragments (W already tf32 bits in smem)
    uint32_t b[4][4][2];
#pragma unroll
    for (int kt = 0; kt < 4; kt++)
#pragma unroll
        for (int nt = 0; nt < 4; nt++)
#pragma unroll
            for (int v = 0; v < 2; v++)
                b[kt][nt][v] = __float_as_uint(wp[(8 * kt + 4 * v + tg) * 36 + 8 * nt + g]);

    // ---- MMA: 2 x 4 x 4 tiles
    float c[2][4][4];
#pragma unroll
    for (int mt = 0; mt < 2; mt++)
#pragma unroll
        for (int nt = 0; nt < 4; nt++) {
#pragma unroll
            for (int r = 0; r < 4; r++) c[mt][nt][r] = 0.f;
#pragma unroll
            for (int kt = 0; kt < 4; kt++)
                mma_tf32(c[mt][nt], ua[mt][kt], b[kt][nt]);
        }

    // ---- log + store (C frag: r: 0=(u0,d0) 1=(u0,d1) 2=(u1,d0) 3=(u1,d1))
#pragma unroll
    for (int mt = 0; mt < 2; mt++)
#pragma unroll
        for (int nt = 0; nt < 4; nt++)
#pragma unroll
            for (int r = 0; r < 4; r++) {
                const int u = r >> 1, d = r & 1;
                const int row = 16 * mt + 8 * u + g;
                const int col = 8 * nt + 2 * tg + d;
                po[row * 36 + col] = fmaf(lg2f(c[mt][nt][r]), LN2, mx[mt][u]);
            }
}

// Stage nm weight matrices as tf32 bits, row-major stride 36. All 128 threads.
template <int NM>
__device__ __forceinline__ void stage_wt(float* dst, const float* __restrict__ src,
                                         int tid) {
#pragma unroll
    for (int j = 0; j < NM * 8; j++) {
        const int idx = tid + j * 128;
        const int m = idx >> 10, rc = idx & 1023;
        dst[m * SLOT_FL + (rc >> 5) * 36 + (rc & 31)] =
            __uint_as_float(cvt_tf32(src[idx]));
    }
}

// ---------------------------------------------------------------------------
// Tree kernel (MMA): 16-leaf subtree -> 1 node, 32 batches, 4 warps.
// Grid: (IN_F/16, 16). smem: 8 value slots + 2 x 4 W slots = 73728 B.
// ---------------------------------------------------------------------------
#define VAL_FL  (8 * SLOT_FL)
#define WBUF_FL (4 * SLOT_FL)
#define SMEM_MMA_FL (VAL_FL + 2 * WBUF_FL)   // 18432 floats

template <int IN_F>
__global__ void __launch_bounds__(128, 3)
pc_tree_mma(const float* __restrict__ in, const float* __restrict__ W,
            float* __restrict__ outp) {
    extern __shared__ float sm[];
    float* val = sm;
    float* wb0 = sm + VAL_FL;
    float* wb1 = wb0 + WBUF_FL;

    const int s   = blockIdx.x;
    const int B0  = blockIdx.y * 32;
    const int tid = threadIdx.x;
    const int w = tid >> 5, lane = tid & 31;

    const int o0 = 2048 - IN_F;
    const int o1 = o0 + IN_F / 2, o2 = o1 + IN_F / 4, o3 = o2 + IN_F / 8;

    // ---- stage L0a weights + all 8 p-slots (p = leaf-pair sums) ----
    stage_wt<4>(wb0, W + (size_t)(o0 + s * 8) * 1024, tid);
    {
        const int k4 = lane & 7, bo = lane >> 3;
#pragma unroll
        for (int ns = 0; ns < 2; ns++) {
            const int n = 2 * w + ns;
            float* slot = val + n * SLOT_FL;
            const float4* xA = (const float4*)(in + ((size_t)B0 * IN_F + (size_t)s * 16 + 2 * n) * 32);
            const float4* xB = xA + 8;   // sibling leaf, +32 floats
#pragma unroll
            for (int i = 0; i < 8; i++) {
                const int bb = i * 4 + bo;
                const size_t roff = (size_t)bb * IN_F * 8;
                float4 va = xA[roff + k4];
                float4 vb = xB[roff + k4];
                float4 p{va.x + vb.x, va.y + vb.y, va.z + vb.z, va.w + vb.w};
                *(float4*)(slot + bb * 36 + 4 * k4) = p;
            }
        }
    }
    __syncthreads();

    // R0: L0 nodes 0..3 (in place)
    node_mma<false>(val + w * SLOT_FL, val + w * SLOT_FL,
                    wb0 + w * SLOT_FL, val + w * SLOT_FL, lane);
    stage_wt<4>(wb1, W + (size_t)(o0 + s * 8 + 4) * 1024, tid);
    __syncthreads();

    // R1: L0 nodes 4..7
    node_mma<false>(val + (4 + w) * SLOT_FL, val + (4 + w) * SLOT_FL,
                    wb1 + w * SLOT_FL, val + (4 + w) * SLOT_FL, lane);
    stage_wt<4>(wb0, W + (size_t)(o1 + s * 4) * 1024, tid);
    __syncthreads();

    // R2: L1, node j=w: slots 2w,2w+1 -> 2w
    node_mma<true>(val + 2 * w * SLOT_FL, val + (2 * w + 1) * SLOT_FL,
                   wb0 + w * SLOT_FL, val + 2 * w * SLOT_FL, lane);
    stage_wt<2>(wb1, W + (size_t)(o2 + s * 2) * 1024, tid);
    __syncthreads();

    // R3: L2, warps 0,1: slots 4w,4w+2 -> 4w
    if (w < 2)
        node_mma<true>(val + 4 * w * SLOT_FL, val + (4 * w + 2) * SLOT_FL,
                       wb1 + w * SLOT_FL, val + 4 * w * SLOT_FL, lane);
    stage_wt<1>(wb0, W + (size_t)(o3 + s) * 1024, tid);
    __syncthreads();

    // R4: L3 root: slots 0,4 -> slot 0
    if (w == 0)
        node_mma<true>(val, val + 4 * SLOT_FL, wb0, val, lane);
    __syncthreads();

    // ---- write root to global ----
    constexpr int OUT_F = IN_F / 16;
#pragma unroll
    for (int i = 0; i < 2; i++) {
        const int idx = tid + i * 128;
        const int bb = idx >> 3, k4 = idx & 7;
        float4 v = *(const float4*)(val + bb * 36 + 4 * k4);
        *(float4*)(outp + ((size_t)(B0 + bb) * OUT_F + s) * 32 + 4 * k4) = v;
    }
}

// ---------------------------------------------------------------------------
// FP32 scalar node path (tail kernel only)
// ---------------------------------------------------------------------------
__device__ __forceinline__ void node_core(float p[32], uint32_t waddr,
                                          float* po, int ostr) {
    float m0 = p[0], m1 = p[1], m2 = p[2], m3 = p[3];
#pragma unroll
    for (int k = 4; k < 32; k += 4) {
        m0 = fmaxf(m0, p[k]);     m1 = fmaxf(m1, p[k + 1]);
        m2 = fmaxf(m2, p[k + 2]); m3 = fmaxf(m3, p[k + 3]);
    }
    const float mx = fmaxf(fmaxf(m0, m1), fmaxf(m2, m3));
    const float nmx = -mx * L2E;
#pragma unroll
    for (int k = 0; k < 32; k++) p[k] = ex2f(fmaf(p[k], L2E, nmx));
    ull acc[16];
#pragma unroll
    for (int q = 0; q < 16; q++) acc[q] = 0ULL;
#pragma unroll 4
    for (int i = 0; i < 32; i++) {
        const ull ep = pack2(p[i]);
        const uint32_t ra = waddr + (uint32_t)i * 128u;
#pragma unroll
        for (int q = 0; q < 8; q++) {
            ull w0, w1; lds2(w0, w1, ra + (uint32_t)q * 16u);
            acc[2 * q]     = fma2(ep, w0, acc[2 * q]);
            acc[2 * q + 1] = fma2(ep, w1, acc[2 * q + 1]);
        }
    }
#pragma unroll
    for (int q = 0; q < 16; q++) {
        float y0, y1; unpack2(acc[q], y0, y1);
        po[(2 * q)     * ostr] = fmaf(lg2f(y0), LN2, mx);
        po[(2 * q + 1) * ostr] = fmaf(lg2f(y1), LN2, mx);
    }
}

__device__ __forceinline__ void node_g(const float* __restrict__ gp,
                                       uint32_t waddr, float* po, int ostr) {
    float p[32];
    const float4* g4 = (const float4*)gp;
#pragma unroll
    for (int q = 0; q < 8; q++) {
        float4 a = g4[q], bb = g4[q + 8];
        p[4 * q]     = a.x + bb.x; p[4 * q + 1] = a.y + bb.y;
        p[4 * q + 2] = a.z + bb.z; p[4 * q + 3] = a.w + bb.w;
    }
    node_core(p, waddr, po, ostr);
}

__device__ __forceinline__ void node_s(const float* sa, const float* sb, int istr,
                                       uint32_t waddr, float* po, int ostr) {
    float p[32];
#pragma unroll
    for (int k = 0; k < 32; k++) p[k] = sa[k * istr] + sb[k * istr];
    node_core(p, waddr, po, ostr);
}

// ---------------------------------------------------------------------------
// Tail: F=8 -> root + mixture (fp32). Grid 16 x 256 thr, 32 batches each.
// ---------------------------------------------------------------------------
#define SMEM_TAIL_FLOATS (8 * 1024 + 7 * 1024 + 32)

__global__ void __launch_bounds__(256, 2)
pc_tail8(const float* __restrict__ in, const float* __restrict__ W,
         const float* __restrict__ mlw, float* __restrict__ outp) {
    extern __shared__ float sm[];
    float* val = sm;
    float* wb  = sm + 8192;
    float* lw  = sm + 8192 + 7168;

    const int B0  = blockIdx.x * 32;
    const int tid = threadIdx.x;
    const int w = tid >> 5, lane = tid & 31;

    {
        const float4* src = (const float4*)(W + (size_t)2040 * 1024);
        float4* dst = (float4*)wb;
#pragma unroll
        for (int i = 0; i < 7; i++) dst[tid + i * 256] = src[tid + i * 256];
    }
    if (tid < 32) lw[tid] = mlw[tid];
    __syncthreads();

    if (w < 4) {
        const float* gp = in + ((size_t)(B0 + lane) * 8 + 2 * w) * 32;
        node_g(gp, s2u(wb + w * 1024), val + w * 1024 + lane, 32);
    }
    __syncthreads();

    if (w < 2)
        node_s(val + (2 * w) * 1024 + lane, val + (2 * w + 1) * 1024 + lane, 32,
               s2u(wb + (4 + w) * 1024), val + (2 * w) * 1024 + lane, 32);
    __syncthreads();

    if (w == 0)
        node_s(val + lane, val + 2 * 1024 + lane, 32,
               s2u(wb + 6 * 1024), val + lane, 32);
    __syncthreads();

    if (tid < 32) {
        const int b2 = tid;
        float m1 = lw[0];
        for (int k = 1; k < 32; k++) m1 = fmaxf(m1, lw[k]);
        float s1 = 0.f;
        for (int k = 0; k < 32; k++) s1 += ex2f((lw[k] - m1) * L2E);
        const float lse = fmaf(lg2f(s1), LN2, m1);

        float m2 = -1e30f;
        for (int k = 0; k < 32; k++)
            m2 = fmaxf(m2, 2.f * val[k * 32 + b2] + lw[k] - lse);
        float s2 = 0.f;
        for (int k = 0; k < 32; k++)
            s2 += ex2f((2.f * val[k * 32 + b2] + lw[k] - lse - m2) * L2E);
        outp[B0 + b2] = fmaf(lg2f(s2), LN2, m2);
    }
}

// ---------------------------------------------------------------------------
// Launch. Inputs: x f32[512,2048,32], weights f32[2047,32,32],
// fold_idx i32 (trivial (2f,2f+1) pairing -> computed), mix_logw f32[32].
// Output: f32[512].
// ---------------------------------------------------------------------------
extern "C" void kernel_launch(void* const* d_in, const int* in_sizes, int n_in,
                              void* d_out, int out_size) {
    const float* x   = (const float*)d_in[0];
    const float* W   = (const float*)d_in[1];
    const float* mlw = (const float*)d_in[3];
    float* out = (float*)d_out;

    float* g1; cudaGetSymbolAddress((void**)&g1, g_l128);
    float* g2; cudaGetSymbolAddress((void**)&g2, g_l8);

    const int smem_mma  = SMEM_MMA_FL * sizeof(float);
    const int smem_tail = SMEM_TAIL_FLOATS * sizeof(float);
    cudaFuncSetAttribute(pc_tree_mma<2048>, cudaFuncAttributeMaxDynamicSharedMemorySize, smem_mma);
    cudaFuncSetAttribute(pc_tree_mma<128>,  cudaFuncAttributeMaxDynamicSharedMemorySize, smem_mma);
    cudaFuncSetAttribute(pc_tail8,          cudaFuncAttributeMaxDynamicSharedMemorySize, smem_tail);

    pc_tree_mma<2048><<<dim3(128, 16), 128, smem_mma>>>(x,  W, g1);
    pc_tree_mma<128> <<<dim3(8, 16),   128, smem_mma>>>(g1, W, g2);
    pc_tail8         <<<16,            256, smem_tail>>>(g2, W, mlw, out);
}

// round 7
// speedup vs baseline: 1.8447x; 1.0031x over previous
#include <cuda_runtime.h>
#include <cstdint>

typedef unsigned long long ull;

#define L2E 1.4426950408889634f
#define LN2 0.6931471805599453f

// Inter-kernel scratch (static device memory: allowed)
__device__ float g_l128[(size_t)512 * 128 * 32];   // 8 MB
__device__ float g_l8 [(size_t)512 * 8 * 32];      // 512 KB

// ---------------------------------------------------------------------------
// Low-level helpers
// ---------------------------------------------------------------------------
__device__ __forceinline__ float ex2f(float x) {
    float r; asm("ex2.approx.f32 %0, %1;" : "=f"(r) : "f"(x)); return r;
}
__device__ __forceinline__ float lg2f(float x) {
    float r; asm("lg2.approx.f32 %0, %1;" : "=f"(r) : "f"(x)); return r;
}
__device__ __forceinline__ uint32_t cvt_tf32(float x) {
    uint32_t r; asm("cvt.rna.tf32.f32 %0, %1;" : "=r"(r) : "f"(x)); return r;
}
__device__ __forceinline__ uint32_t s2u(const void* p) {
    return (uint32_t)__cvta_generic_to_shared(p);
}
__device__ __forceinline__ ull pack2(float x) {
    ull r; asm("mov.b64 %0, {%1, %1};" : "=l"(r) : "f"(x)); return r;
}
__device__ __forceinline__ void unpack2(ull v, float& lo, float& hi) {
    asm("mov.b64 {%0, %1}, %2;" : "=f"(lo), "=f"(hi) : "l"(v));
}
__device__ __forceinline__ ull fma2(ull a, ull b, ull c) {
    ull d; asm("fma.rn.f32x2 %0, %1, %2, %3;" : "=l"(d) : "l"(a), "l"(b), "l"(c)); return d;
}
__device__ __forceinline__ void lds2(ull& a, ull& b, uint32_t addr) {
    asm("ld.shared.v2.u64 {%0, %1}, [%2];" : "=l"(a), "=l"(b) : "r"(addr));
}

// m16n8k8 tf32 mma, D += A*B
__device__ __forceinline__ void mma_tf32(float c[4], const uint32_t a[4], const uint32_t b[2]) {
    asm("mma.sync.aligned.m16n8k8.row.col.f32.tf32.tf32.f32 "
        "{%0,%1,%2,%3}, {%4,%5,%6,%7}, {%8,%9}, {%0,%1,%2,%3};"
        : "+f"(c[0]), "+f"(c[1]), "+f"(c[2]), "+f"(c[3])
        : "r"(a[0]), "r"(a[1]), "r"(a[2]), "r"(a[3]), "r"(b[0]), "r"(b[1]));
}

// ---------------------------------------------------------------------------
// MMA node: warp computes one node for 32 batches.
// Value slots: row-major [b*36 + k] (stride 36 -> conflict-free A-frag LDS).
// W slot: tf32 bits, row-major [k*36 + j] (conflict-free B-frag LDS).
// ---------------------------------------------------------------------------
#define SLOT_FL (32 * 36)        // 1152 floats per slot

template <bool DUAL>
__device__ __forceinline__ void node_mma(const float* pa, const float* pb,
                                         const float* wp, float* po, int lane) {
    const int g = lane >> 2, tg = lane & 3;

    // ---- A fragments: a[mt][kt][r], r: 0=(u0,v0) 1=(u1,v0) 2=(u0,v1) 3=(u1,v1)
    float a[2][4][4];
#pragma unroll
    for (int mt = 0; mt < 2; mt++)
#pragma unroll
        for (int kt = 0; kt < 4; kt++)
#pragma unroll
            for (int r = 0; r < 4; r++) {
                const int row = 16 * mt + 8 * (r & 1) + g;
                const int col = 8 * kt + 4 * (r >> 1) + tg;
                float v = pa[row * 36 + col];
                if (DUAL) v += pb[row * 36 + col];
                a[mt][kt][r] = v;
            }

    // ---- row max per (mt, u)
    float mx[2][2];
#pragma unroll
    for (int mt = 0; mt < 2; mt++)
#pragma unroll
        for (int u = 0; u < 2; u++) {
            float m = fmaxf(a[mt][0][u], a[mt][0][u + 2]);
#pragma unroll
            for (int kt = 1; kt < 4; kt++)
                m = fmaxf(m, fmaxf(a[mt][kt][u], a[mt][kt][u + 2]));
            m = fmaxf(m, __shfl_xor_sync(0xffffffffu, m, 1));
            m = fmaxf(m, __shfl_xor_sync(0xffffffffu, m, 2));
            mx[mt][u] = m;
        }

    // ---- e = exp2((p - m) * L2E) as tf32-truncated bits (in place)
    uint32_t ua[2][4][4];
#pragma unroll
    for (int mt = 0; mt < 2; mt++)
#pragma unroll
        for (int kt = 0; kt < 4; kt++)
#pragma unroll
            for (int r = 0; r < 4; r++) {
                const float nm = -mx[mt][r & 1] * L2E;
                ua[mt][kt][r] = __float_as_uint(ex2f(fmaf(a[mt][kt][r], L2E, nm)));
            }

    // ---- per-nt: load B frags, 2 mt-tiles of MMA, log + STS.64 stores
#pragma unroll
    for (int nt = 0; nt < 4; nt++) {
        uint32_t b[4][2];
#pragma unroll
        for (int kt = 0; kt < 4; kt++) {
            b[kt][0] = __float_as_uint(wp[(8 * kt + tg) * 36 + 8 * nt + g]);
            b[kt][1] = __float_as_uint(wp[(8 * kt + 4 + tg) * 36 + 8 * nt + g]);
        }
#pragma unroll
        for (int mt = 0; mt < 2; mt++) {
            float c[4] = {0.f, 0.f, 0.f, 0.f};
#pragma unroll
            for (int kt = 0; kt < 4; kt++)
                mma_tf32(c, ua[mt][kt], b[kt]);
#pragma unroll
            for (int u = 0; u < 2; u++) {
                const int row = 16 * mt + 8 * u + g;
                float2 o;
                o.x = fmaf(lg2f(c[2 * u]),     LN2, mx[mt][u]);
                o.y = fmaf(lg2f(c[2 * u + 1]), LN2, mx[mt][u]);
                *(float2*)(po + row * 36 + 8 * nt + 2 * tg) = o;
            }
        }
    }
}

// Stage NM weight matrices as tf32 bits, row-major stride 36.
// Lanes j-major: LDG coalesced, STS bank (4k+j) conflict-free.
template <int NM>
__device__ __forceinline__ void stage_wt(float* dst, const float* __restrict__ src,
                                         int tid) {
#pragma unroll
    for (int j = 0; j < NM * 8; j++) {
        const int idx = tid + j * 128;
        const int m = idx >> 10, rc = idx & 1023;
        dst[m * SLOT_FL + (rc >> 5) * 36 + (rc & 31)] =
            __uint_as_float(cvt_tf32(src[idx]));
    }
}

// ---------------------------------------------------------------------------
// Tree kernel (MMA): 16-leaf subtree -> 1 node, 32 batches, 4 warps.
// Grid: (IN_F/16, 16). smem: 8 value slots + 4 W slots = 55296 B -> 4 blocks/SM.
// ---------------------------------------------------------------------------
#define VAL_FL  (8 * SLOT_FL)
#define WBUF_FL (4 * SLOT_FL)
#define SMEM_MMA_FL (VAL_FL + WBUF_FL)   // 13824 floats = 55296 B

template <int IN_F>
__global__ void __launch_bounds__(128, 4)
pc_tree_mma(const float* __restrict__ in, const float* __restrict__ W,
            float* __restrict__ outp) {
    extern __shared__ float sm[];
    float* val = sm;
    float* wb  = sm + VAL_FL;

    const int s   = blockIdx.x;
    const int B0  = blockIdx.y * 32;
    const int tid = threadIdx.x;
    const int w = tid >> 5, lane = tid & 31;

    const int o0 = 2048 - IN_F;
    const int o1 = o0 + IN_F / 2, o2 = o1 + IN_F / 4, o3 = o2 + IN_F / 8;

    // ---- prologue: stage L0a weights + all 8 p-slots (p = leaf-pair sums) ----
    stage_wt<4>(wb, W + (size_t)(o0 + s * 8) * 1024, tid);
    {
        const int k4 = lane & 7, bo = lane >> 3;
#pragma unroll
        for (int ns = 0; ns < 2; ns++) {
            const int n = 2 * w + ns;
            float* slot = val + n * SLOT_FL;
            const float4* xA = (const float4*)(in + ((size_t)B0 * IN_F + (size_t)s * 16 + 2 * n) * 32);
            const float4* xB = xA + 8;   // sibling leaf, +32 floats
#pragma unroll
            for (int i = 0; i < 8; i++) {
                const int bb = i * 4 + bo;
                const size_t roff = (size_t)bb * IN_F * 8;
                float4 va = xA[roff + k4];
                float4 vb = xB[roff + k4];
                float4 p{va.x + vb.x, va.y + vb.y, va.z + vb.z, va.w + vb.w};
                *(float4*)(slot + bb * 36 + 4 * k4) = p;
            }
        }
    }
    __syncthreads();

    // R0: L0 nodes 0..3 (in place)
    node_mma<false>(val + w * SLOT_FL, val + w * SLOT_FL,
                    wb + w * SLOT_FL, val + w * SLOT_FL, lane);
    __syncthreads();
    stage_wt<4>(wb, W + (size_t)(o0 + s * 8 + 4) * 1024, tid);
    __syncthreads();

    // R1: L0 nodes 4..7
    node_mma<false>(val + (4 + w) * SLOT_FL, val + (4 + w) * SLOT_FL,
                    wb + w * SLOT_FL, val + (4 + w) * SLOT_FL, lane);
    __syncthreads();
    stage_wt<4>(wb, W + (size_t)(o1 + s * 4) * 1024, tid);
    __syncthreads();

    // R2: L1, node j=w: slots 2w,2w+1 -> 2w
    node_mma<true>(val + 2 * w * SLOT_FL, val + (2 * w + 1) * SLOT_FL,
                   wb + w * SLOT_FL, val + 2 * w * SLOT_FL, lane);
    __syncthreads();
    stage_wt<2>(wb, W + (size_t)(o2 + s * 2) * 1024, tid);
    __syncthreads();

    // R3: L2, warps 0,1: slots 4w,4w+2 -> 4w
    if (w < 2)
        node_mma<true>(val + 4 * w * SLOT_FL, val + (4 * w + 2) * SLOT_FL,
                       wb + w * SLOT_FL, val + 4 * w * SLOT_FL, lane);
    __syncthreads();
    stage_wt<1>(wb, W + (size_t)(o3 + s) * 1024, tid);
    __syncthreads();

    // R4: L3 root: slots 0,4 -> slot 0
    if (w == 0)
        node_mma<true>(val, val + 4 * SLOT_FL, wb, val, lane);
    __syncthreads();

    // ---- write root to global ----
    constexpr int OUT_F = IN_F / 16;
#pragma unroll
    for (int i = 0; i < 2; i++) {
        const int idx = tid + i * 128;
        const int bb = idx >> 3, k4 = idx & 7;
        float4 v = *(const float4*)(val + bb * 36 + 4 * k4);
        *(float4*)(outp + ((size_t)(B0 + bb) * OUT_F + s) * 32 + 4 * k4) = v;
    }
}

// ---------------------------------------------------------------------------
// FP32 scalar node path (tail kernel only)
// ---------------------------------------------------------------------------
__device__ __forceinline__ void node_core(float p[32], uint32_t waddr,
                                          float* po, int ostr) {
    float m0 = p[0], m1 = p[1], m2 = p[2], m3 = p[3];
#pragma unroll
    for (int k = 4; k < 32; k += 4) {
        m0 = fmaxf(m0, p[k]);     m1 = fmaxf(m1, p[k + 1]);
        m2 = fmaxf(m2, p[k + 2]); m3 = fmaxf(m3, p[k + 3]);
    }
    const float mx = fmaxf(fmaxf(m0, m1), fmaxf(m2, m3));
    const float nmx = -mx * L2E;
#pragma unroll
    for (int k = 0; k < 32; k++) p[k] = ex2f(fmaf(p[k], L2E, nmx));
    ull acc[16];
#pragma unroll
    for (int q = 0; q < 16; q++) acc[q] = 0ULL;
#pragma unroll 4
    for (int i = 0; i < 32; i++) {
        const ull ep = pack2(p[i]);
        const uint32_t ra = waddr + (uint32_t)i * 128u;
#pragma unroll
        for (int q = 0; q < 8; q++) {
            ull w0, w1; lds2(w0, w1, ra + (uint32_t)q * 16u);
            acc[2 * q]     = fma2(ep, w0, acc[2 * q]);
            acc[2 * q + 1] = fma2(ep, w1, acc[2 * q + 1]);
        }
    }
#pragma unroll
    for (int q = 0; q < 16; q++) {
        float y0, y1; unpack2(acc[q], y0, y1);
        po[(2 * q)     * ostr] = fmaf(lg2f(y0), LN2, mx);
        po[(2 * q + 1) * ostr] = fmaf(lg2f(y1), LN2, mx);
    }
}

__device__ __forceinline__ void node_g(const float* __restrict__ gp,
                                       uint32_t waddr, float* po, int ostr) {
    float p[32];
    const float4* g4 = (const float4*)gp;
#pragma unroll
    for (int q = 0; q < 8; q++) {
        float4 a = g4[q], bb = g4[q + 8];
        p[4 * q]     = a.x + bb.x; p[4 * q + 1] = a.y + bb.y;
        p[4 * q + 2] = a.z + bb.z; p[4 * q + 3] = a.w + bb.w;
    }
    node_core(p, waddr, po, ostr);
}

__device__ __forceinline__ void node_s(const float* sa, const float* sb, int istr,
                                       uint32_t waddr, float* po, int ostr) {
    float p[32];
#pragma unroll
    for (int k = 0; k < 32; k++) p[k] = sa[k * istr] + sb[k * istr];
    node_core(p, waddr, po, ostr);
}

// ---------------------------------------------------------------------------
// Tail: F=8 -> root + mixture (fp32). Grid 16 x 256 thr, 32 batches each.
// ---------------------------------------------------------------------------
#define SMEM_TAIL_FLOATS (8 * 1024 + 7 * 1024 + 32)

__global__ void __launch_bounds__(256, 2)
pc_tail8(const float* __restrict__ in, const float* __restrict__ W,
         const float* __restrict__ mlw, float* __restrict__ outp) {
    extern __shared__ float sm[];
    float* val = sm;
    float* wb  = sm + 8192;
    float* lw  = sm + 8192 + 7168;

    const int B0  = blockIdx.x * 32;
    const int tid = threadIdx.x;
    const int w = tid >> 5, lane = tid & 31;

    {
        const float4* src = (const float4*)(W + (size_t)2040 * 1024);
        float4* dst = (float4*)wb;
#pragma unroll
        for (int i = 0; i < 7; i++) dst[tid + i * 256] = src[tid + i * 256];
    }
    if (tid < 32) lw[tid] = mlw[tid];
    __syncthreads();

    if (w < 4) {
        const float* gp = in + ((size_t)(B0 + lane) * 8 + 2 * w) * 32;
        node_g(gp, s2u(wb + w * 1024), val + w * 1024 + lane, 32);
    }
    __syncthreads();

    if (w < 2)
        node_s(val + (2 * w) * 1024 + lane, val + (2 * w + 1) * 1024 + lane, 32,
               s2u(wb + (4 + w) * 1024), val + (2 * w) * 1024 + lane, 32);
    __syncthreads();

    if (w == 0)
        node_s(val + lane, val + 2 * 1024 + lane, 32,
               s2u(wb + 6 * 1024), val + lane, 32);
    __syncthreads();

    if (tid < 32) {
        const int b2 = tid;
        float m1 = lw[0];
        for (int k = 1; k < 32; k++) m1 = fmaxf(m1, lw[k]);
        float s1 = 0.f;
        for (int k = 0; k < 32; k++) s1 += ex2f((lw[k] - m1) * L2E);
        const float lse = fmaf(lg2f(s1), LN2, m1);

        float m2 = -1e30f;
        for (int k = 0; k < 32; k++)
            m2 = fmaxf(m2, 2.f * val[k * 32 + b2] + lw[k] - lse);
        float s2 = 0.f;
        for (int k = 0; k < 32; k++)
            s2 += ex2f((2.f * val[k * 32 + b2] + lw[k] - lse - m2) * L2E);
        outp[B0 + b2] = fmaf(lg2f(s2), LN2, m2);
    }
}

// ---------------------------------------------------------------------------
// Launch. Inputs: x f32[512,2048,32], weights f32[2047,32,32],
// fold_idx i32 (trivial (2f,2f+1) pairing -> computed), mix_logw f32[32].
// Output: f32[512].
// ---------------------------------------------------------------------------
extern "C" void kernel_launch(void* const* d_in, const int* in_sizes, int n_in,
                              void* d_out, int out_size) {
    const float* x   = (const float*)d_in[0];
    const float* W   = (const float*)d_in[1];
    const float* mlw = (const float*)d_in[3];
    float* out = (float*)d_out;

    float* g1; cudaGetSymbolAddress((void**)&g1, g_l128);
    float* g2; cudaGetSymbolAddress((void**)&g2, g_l8);

    const int smem_mma  = SMEM_MMA_FL * sizeof(float);
    const int smem_tail = SMEM_TAIL_FLOATS * sizeof(float);
    cudaFuncSetAttribute(pc_tree_mma<2048>, cudaFuncAttributeMaxDynamicSharedMemorySize, smem_mma);
    cudaFuncSetAttribute(pc_tree_mma<128>,  cudaFuncAttributeMaxDynamicSharedMemorySize, smem_mma);
    cudaFuncSetAttribute(pc_tail8,          cudaFuncAttributeMaxDynamicSharedMemorySize, smem_tail);

    pc_tree_mma<2048><<<dim3(128, 16), 128, smem_mma>>>(x,  W, g1);
    pc_tree_mma<128> <<<dim3(8, 16),   128, smem_mma>>>(g1, W, g2);
    pc_tail8         <<<16,            256, smem_tail>>>(g2, W, mlw, out);
}

// round 8
// speedup vs baseline: 1.9420x; 1.0527x over previous
#include <cuda_runtime.h>
#include <cstdint>

typedef unsigned long long ull;

#define L2E 1.4426950408889634f
#define LN2 0.6931471805599453f

// Inter-kernel scratch (static device memory: allowed)
__device__ float g_l128[(size_t)512 * 128 * 32];   // 8 MB
__device__ float g_l8 [(size_t)512 * 8 * 32];      // 512 KB

// ---------------------------------------------------------------------------
// Low-level helpers
// ---------------------------------------------------------------------------
__device__ __forceinline__ float ex2f(float x) {
    float r; asm("ex2.approx.f32 %0, %1;" : "=f"(r) : "f"(x)); return r;
}
__device__ __forceinline__ float lg2f(float x) {
    float r; asm("lg2.approx.f32 %0, %1;" : "=f"(r) : "f"(x)); return r;
}
__device__ __forceinline__ uint32_t s2u(const void* p) {
    return (uint32_t)__cvta_generic_to_shared(p);
}
__device__ __forceinline__ ull pack2(float x) {
    ull r; asm("mov.b64 %0, {%1, %1};" : "=l"(r) : "f"(x)); return r;
}
__device__ __forceinline__ void unpack2(ull v, float& lo, float& hi) {
    asm("mov.b64 {%0, %1}, %2;" : "=f"(lo), "=f"(hi) : "l"(v));
}
__device__ __forceinline__ ull fma2(ull a, ull b, ull c) {
    ull d; asm("fma.rn.f32x2 %0, %1, %2, %3;" : "=l"(d) : "l"(a), "l"(b), "l"(c)); return d;
}
__device__ __forceinline__ void lds2(ull& a, ull& b, uint32_t addr) {
    asm("ld.shared.v2.u64 {%0, %1}, [%2];" : "=l"(a), "=l"(b) : "r"(addr));
}
__device__ __forceinline__ void cp_async16(uint32_t dst, const void* src) {
    asm volatile("cp.async.cg.shared.global [%0], [%1], 16;" :: "r"(dst), "l"(src));
}
__device__ __forceinline__ void cp_commit() {
    asm volatile("cp.async.commit_group;");
}
template <int N>
__device__ __forceinline__ void cp_wait() {
    asm volatile("cp.async.wait_group %0;" :: "n"(N));
}

// m16n8k8 tf32 mma, D += A*B
__device__ __forceinline__ void mma_tf32(float c[4], const uint32_t a[4], const uint32_t b[2]) {
    asm("mma.sync.aligned.m16n8k8.row.col.f32.tf32.tf32.f32 "
        "{%0,%1,%2,%3}, {%4,%5,%6,%7}, {%8,%9}, {%0,%1,%2,%3};"
        : "+f"(c[0]), "+f"(c[1]), "+f"(c[2]), "+f"(c[3])
        : "r"(a[0]), "r"(a[1]), "r"(a[2]), "r"(a[3]), "r"(b[0]), "r"(b[1]));
}

// ---------------------------------------------------------------------------
// MMA node: warp computes one node for 32 batches.
// Value slots: row-major [b*36 + k] (stride 36 -> conflict-free A-frag LDS).
// W slot: raw f32 bits, row-major [k*36 + j] (tf32 MMA truncates mantissa).
// ---------------------------------------------------------------------------
#define SLOT_FL (32 * 36)        // 1152 floats per slot

template <bool DUAL>
__device__ __forceinline__ void node_mma(const float* pa, const float* pb,
                                         const float* wp, float* po, int lane) {
    const int g = lane >> 2, tg = lane & 3;

    // ---- A fragments: a[mt][kt][r], r: 0=(u0,v0) 1=(u1,v0) 2=(u0,v1) 3=(u1,v1)
    float a[2][4][4];
#pragma unroll
    for (int mt = 0; mt < 2; mt++)
#pragma unroll
        for (int kt = 0; kt < 4; kt++)
#pragma unroll
            for (int r = 0; r < 4; r++) {
                const int row = 16 * mt + 8 * (r & 1) + g;
                const int col = 8 * kt + 4 * (r >> 1) + tg;
                float v = pa[row * 36 + col];
                if (DUAL) v += pb[row * 36 + col];
                a[mt][kt][r] = v;
            }

    // ---- row max per (mt, u)
    float mx[2][2];
#pragma unroll
    for (int mt = 0; mt < 2; mt++)
#pragma unroll
        for (int u = 0; u < 2; u++) {
            float m = fmaxf(a[mt][0][u], a[mt][0][u + 2]);
#pragma unroll
            for (int kt = 1; kt < 4; kt++)
                m = fmaxf(m, fmaxf(a[mt][kt][u], a[mt][kt][u + 2]));
            m = fmaxf(m, __shfl_xor_sync(0xffffffffu, m, 1));
            m = fmaxf(m, __shfl_xor_sync(0xffffffffu, m, 2));
            mx[mt][u] = m;
        }

    // ---- e = exp2((p - m) * L2E) as raw f32 bits (tf32 MMA truncates)
    uint32_t ua[2][4][4];
#pragma unroll
    for (int mt = 0; mt < 2; mt++)
#pragma unroll
        for (int kt = 0; kt < 4; kt++)
#pragma unroll
            for (int r = 0; r < 4; r++) {
                const float nm = -mx[mt][r & 1] * L2E;
                ua[mt][kt][r] = __float_as_uint(ex2f(fmaf(a[mt][kt][r], L2E, nm)));
            }

    // ---- per-nt: load B frags, 2 mt-tiles of MMA, log + STS.64 stores
#pragma unroll
    for (int nt = 0; nt < 4; nt++) {
        uint32_t b[4][2];
#pragma unroll
        for (int kt = 0; kt < 4; kt++) {
            b[kt][0] = __float_as_uint(wp[(8 * kt + tg) * 36 + 8 * nt + g]);
            b[kt][1] = __float_as_uint(wp[(8 * kt + 4 + tg) * 36 + 8 * nt + g]);
        }
#pragma unroll
        for (int mt = 0; mt < 2; mt++) {
            float c[4] = {0.f, 0.f, 0.f, 0.f};
#pragma unroll
            for (int kt = 0; kt < 4; kt++)
                mma_tf32(c, ua[mt][kt], b[kt]);
#pragma unroll
            for (int u = 0; u < 2; u++) {
                const int row = 16 * mt + 8 * u + g;
                float2 o;
                o.x = fmaf(lg2f(c[2 * u]),     LN2, mx[mt][u]);
                o.y = fmaf(lg2f(c[2 * u + 1]), LN2, mx[mt][u]);
                *(float2*)(po + row * 36 + 8 * nt + 2 * tg) = o;
            }
        }
    }
}

// Async-stage NM weight matrices (raw f32) into stride-36 slots via cp.async.
// 16B chunks; LDG fully coalesced; no register cost. Caller commits/waits.
template <int NM>
__device__ __forceinline__ void stage_w_async(uint32_t dst_s,
                                              const float* __restrict__ src,
                                              int tid) {
#pragma unroll
    for (int t = 0; t < NM * 2; t++) {
        const int c = tid + t * 128;
        const int m = c >> 8, rc = c & 255;       // chunk within matrix
        const int row = rc >> 3, col = rc & 7;    // 8 x 16B chunks per row
        cp_async16(dst_s + (uint32_t)(m * SLOT_FL + row * 36 + col * 4) * 4u,
                   src + (size_t)m * 1024 + row * 32 + col * 4);
    }
}

// ---------------------------------------------------------------------------
// Tree kernel (MMA): 16-leaf subtree -> 1 node, 32 batches, 4 warps.
// Grid: (IN_F/16, 16). smem: 8 value slots + 2x4 W slots = 73728 B (3 blk/SM).
// W double-buffered via cp.async: prefetch next layer during current round.
// ---------------------------------------------------------------------------
#define VAL_FL  (8 * SLOT_FL)
#define WBUF_FL (4 * SLOT_FL)
#define SMEM_MMA_FL (VAL_FL + 2 * WBUF_FL)   // 18432 floats = 73728 B

template <int IN_F>
__global__ void __launch_bounds__(128, 3)
pc_tree_mma(const float* __restrict__ in, const float* __restrict__ W,
            float* __restrict__ outp) {
    extern __shared__ float sm[];
    float* val = sm;
    float* wb0 = sm + VAL_FL;
    float* wb1 = wb0 + WBUF_FL;

    const int s   = blockIdx.x;
    const int B0  = blockIdx.y * 32;
    const int tid = threadIdx.x;
    const int w = tid >> 5, lane = tid & 31;
    const uint32_t wb0s = s2u(wb0), wb1s = s2u(wb1);

    const int o0 = 2048 - IN_F;
    const int o1 = o0 + IN_F / 2, o2 = o1 + IN_F / 4, o3 = o2 + IN_F / 8;

    // ---- prologue: async-stage L0a -> wb0, L0b -> wb1; stage p-slots ----
    stage_w_async<4>(wb0s, W + (size_t)(o0 + s * 8) * 1024, tid);
    cp_commit();
    stage_w_async<4>(wb1s, W + (size_t)(o0 + s * 8 + 4) * 1024, tid);
    cp_commit();
    {
        const int k4 = lane & 7, bo = lane >> 3;
#pragma unroll
        for (int ns = 0; ns < 2; ns++) {
            const int n = 2 * w + ns;
            float* slot = val + n * SLOT_FL;
            const float4* xA = (const float4*)(in + ((size_t)B0 * IN_F + (size_t)s * 16 + 2 * n) * 32);
            const float4* xB = xA + 8;   // sibling leaf, +32 floats
#pragma unroll
            for (int i = 0; i < 8; i++) {
                const int bb = i * 4 + bo;
                const size_t roff = (size_t)bb * IN_F * 8;
                float4 va = xA[roff + k4];
                float4 vb = xB[roff + k4];
                float4 p{va.x + vb.x, va.y + vb.y, va.z + vb.z, va.w + vb.w};
                *(float4*)(slot + bb * 36 + 4 * k4) = p;
            }
        }
    }
    cp_wait<1>();               // L0a ready (L0b may still be in flight)
    __syncthreads();

    // R0: L0 nodes 0..3 (wb0), L0b arriving into wb1 meanwhile
    node_mma<false>(val + w * SLOT_FL, val + w * SLOT_FL,
                    wb0 + w * SLOT_FL, val + w * SLOT_FL, lane);
    cp_wait<0>();
    __syncthreads();

    // R1: prefetch L1 -> wb0; compute L0 nodes 4..7 (wb1)
    stage_w_async<4>(wb0s, W + (size_t)(o1 + s * 4) * 1024, tid);
    cp_commit();
    node_mma<false>(val + (4 + w) * SLOT_FL, val + (4 + w) * SLOT_FL,
                    wb1 + w * SLOT_FL, val + (4 + w) * SLOT_FL, lane);
    cp_wait<0>();
    __syncthreads();

    // R2: prefetch L2 -> wb1; compute L1 (wb0): slots 2w,2w+1 -> 2w
    stage_w_async<2>(wb1s, W + (size_t)(o2 + s * 2) * 1024, tid);
    cp_commit();
    node_mma<true>(val + 2 * w * SLOT_FL, val + (2 * w + 1) * SLOT_FL,
                   wb0 + w * SLOT_FL, val + 2 * w * SLOT_FL, lane);
    cp_wait<0>();
    __syncthreads();

    // R3: prefetch L3 -> wb0; warps 0,1 compute L2 (wb1): 4w,4w+2 -> 4w
    stage_w_async<1>(wb0s, W + (size_t)(o3 + s) * 1024, tid);
    cp_commit();
    if (w < 2)
        node_mma<true>(val + 4 * w * SLOT_FL, val + (4 * w + 2) * SLOT_FL,
                       wb1 + w * SLOT_FL, val + 4 * w * SLOT_FL, lane);
    cp_wait<0>();
    __syncthreads();

    // R4: L3 root (wb0): slots 0,4 -> slot 0
    if (w == 0)
        node_mma<true>(val, val + 4 * SLOT_FL, wb0, val, lane);
    __syncthreads();

    // ---- write root to global ----
    constexpr int OUT_F = IN_F / 16;
#pragma unroll
    for (int i = 0; i < 2; i++) {
        const int idx = tid + i * 128;
        const int bb = idx >> 3, k4 = idx & 7;
        float4 v = *(const float4*)(val + bb * 36 + 4 * k4);
        *(float4*)(outp + ((size_t)(B0 + bb) * OUT_F + s) * 32 + 4 * k4) = v;
    }
}

// ---------------------------------------------------------------------------
// FP32 scalar node path (tail kernel only)
// ---------------------------------------------------------------------------
__device__ __forceinline__ void node_core(float p[32], uint32_t waddr,
                                          float* po, int ostr) {
    float m0 = p[0], m1 = p[1], m2 = p[2], m3 = p[3];
#pragma unroll
    for (int k = 4; k < 32; k += 4) {
        m0 = fmaxf(m0, p[k]);     m1 = fmaxf(m1, p[k + 1]);
        m2 = fmaxf(m2, p[k + 2]); m3 = fmaxf(m3, p[k + 3]);
    }
    const float mx = fmaxf(fmaxf(m0, m1), fmaxf(m2, m3));
    const float nmx = -mx * L2E;
#pragma unroll
    for (int k = 0; k < 32; k++) p[k] = ex2f(fmaf(p[k], L2E, nmx));
    ull acc[16];
#pragma unroll
    for (int q = 0; q < 16; q++) acc[q] = 0ULL;
#pragma unroll 4
    for (int i = 0; i < 32; i++) {
        const ull ep = pack2(p[i]);
        const uint32_t ra = waddr + (uint32_t)i * 128u;
#pragma unroll
        for (int q = 0; q < 8; q++) {
            ull w0, w1; lds2(w0, w1, ra + (uint32_t)q * 16u);
            acc[2 * q]     = fma2(ep, w0, acc[2 * q]);
            acc[2 * q + 1] = fma2(ep, w1, acc[2 * q + 1]);
        }
    }
#pragma unroll
    for (int q = 0; q < 16; q++) {
        float y0, y1; unpack2(acc[q], y0, y1);
        po[(2 * q)     * ostr] = fmaf(lg2f(y0), LN2, mx);
        po[(2 * q + 1) * ostr] = fmaf(lg2f(y1), LN2, mx);
    }
}

__device__ __forceinline__ void node_g(const float* __restrict__ gp,
                                       uint32_t waddr, float* po, int ostr) {
    float p[32];
    const float4* g4 = (const float4*)gp;
#pragma unroll
    for (int q = 0; q < 8; q++) {
        float4 a = g4[q], bb = g4[q + 8];
        p[4 * q]     = a.x + bb.x; p[4 * q + 1] = a.y + bb.y;
        p[4 * q + 2] = a.z + bb.z; p[4 * q + 3] = a.w + bb.w;
    }
    node_core(p, waddr, po, ostr);
}

__device__ __forceinline__ void node_s(const float* sa, const float* sb, int istr,
                                       uint32_t waddr, float* po, int ostr) {
    float p[32];
#pragma unroll
    for (int k = 0; k < 32; k++) p[k] = sa[k * istr] + sb[k * istr];
    node_core(p, waddr, po, ostr);
}

// ---------------------------------------------------------------------------
// Tail: F=8 -> root + mixture (fp32). Grid 16 x 256 thr, 32 batches each.
// ---------------------------------------------------------------------------
#define SMEM_TAIL_FLOATS (8 * 1024 + 7 * 1024 + 32)

__global__ void __launch_bounds__(256, 2)
pc_tail8(const float* __restrict__ in, const float* __restrict__ W,
         const float* __restrict__ mlw, float* __restrict__ outp) {
    extern __shared__ float sm[];
    float* val = sm;
    float* wb  = sm + 8192;
    float* lw  = sm + 8192 + 7168;

    const int B0  = blockIdx.x * 32;
    const int tid = threadIdx.x;
    const int w = tid >> 5, lane = tid & 31;

    {
        const float4* src = (const float4*)(W + (size_t)2040 * 1024);
        float4* dst = (float4*)wb;
#pragma unroll
        for (int i = 0; i < 7; i++) dst[tid + i * 256] = src[tid + i * 256];
    }
    if (tid < 32) lw[tid] = mlw[tid];
    __syncthreads();

    if (w < 4) {
        const float* gp = in + ((size_t)(B0 + lane) * 8 + 2 * w) * 32;
        node_g(gp, s2u(wb + w * 1024), val + w * 1024 + lane, 32);
    }
    __syncthreads();

    if (w < 2)
        node_s(val + (2 * w) * 1024 + lane, val + (2 * w + 1) * 1024 + lane, 32,
               s2u(wb + (4 + w) * 1024), val + (2 * w) * 1024 + lane, 32);
    __syncthreads();

    if (w == 0)
        node_s(val + lane, val + 2 * 1024 + lane, 32,
               s2u(wb + 6 * 1024), val + lane, 32);
    __syncthreads();

    if (tid < 32) {
        const int b2 = tid;
        float m1 = lw[0];
        for (int k = 1; k < 32; k++) m1 = fmaxf(m1, lw[k]);
        float s1 = 0.f;
        for (int k = 0; k < 32; k++) s1 += ex2f((lw[k] - m1) * L2E);
        const float lse = fmaf(lg2f(s1), LN2, m1);

        float m2 = -1e30f;
        for (int k = 0; k < 32; k++)
            m2 = fmaxf(m2, 2.f * val[k * 32 + b2] + lw[k] - lse);
        float s2 = 0.f;
        for (int k = 0; k < 32; k++)
            s2 += ex2f((2.f * val[k * 32 + b2] + lw[k] - lse - m2) * L2E);
        outp[B0 + b2] = fmaf(lg2f(s2), LN2, m2);
    }
}

// ---------------------------------------------------------------------------
// Launch. Inputs: x f32[512,2048,32], weights f32[2047,32,32],
// fold_idx i32 (trivial (2f,2f+1) pairing -> computed), mix_logw f32[32].
// Output: f32[512].
// ---------------------------------------------------------------------------
extern "C" void kernel_launch(void* const* d_in, const int* in_sizes, int n_in,
                              void* d_out, int out_size) {
    const float* x   = (const float*)d_in[0];
    const float* W   = (const float*)d_in[1];
    const float* mlw = (const float*)d_in[3];
    float* out = (float*)d_out;

    float* g1; cudaGetSymbolAddress((void**)&g1, g_l128);
    float* g2; cudaGetSymbolAddress((void**)&g2, g_l8);

    const int smem_mma  = SMEM_MMA_FL * sizeof(float);
    const int smem_tail = SMEM_TAIL_FLOATS * sizeof(float);
    cudaFuncSetAttribute(pc_tree_mma<2048>, cudaFuncAttributeMaxDynamicSharedMemorySize, smem_mma);
    cudaFuncSetAttribute(pc_tree_mma<128>,  cudaFuncAttributeMaxDynamicSharedMemorySize, smem_mma);
    cudaFuncSetAttribute(pc_tail8,          cudaFuncAttributeMaxDynamicSharedMemorySize, smem_tail);

    pc_tree_mma<2048><<<dim3(128, 16), 128, smem_mma>>>(x,  W, g1);
    pc_tree_mma<128> <<<dim3(8, 16),   128, smem_mma>>>(g1, W, g2);
    pc_tail8         <<<16,            256, smem_tail>>>(g2, W, mlw, out);
}